// round 1
// baseline (speedup 1.0000x reference)
#include <cuda_runtime.h>
#include <math.h>

// Problem constants (fixed by dataset)
#define B_   16
#define S_   128
#define D_   128
#define E_   64
#define T_   128
#define NTOK (B_ * S_)   // 2048

// ----------------------------------------------------------------------------
// Scratch (static device globals; allocation-free)
// ----------------------------------------------------------------------------
__device__ int   g_cnt1, g_cnt2;
__device__ int   g_list1[NTOK], g_list2[NTOK];
__device__ float g_cbg[D_];                 // tanh(b2)
__device__ float g_base[D_];                // sum(wr)*tanh(b2)+br
__device__ float g_tpart[4 * NTOK * T_];    // tde partials over 4 d-chunks
__device__ float g_cpart[4 * NTOK * D_];    // c   partials over 4 d-chunks
__device__ float g_tde  [NTOK * T_];        // tanh'd tde for active tokens
__device__ float g_delta[NTOK * D_];        // wr[j]*(c_nz - c_bg)
__device__ float g_tok1 [NTOK * D_];        // block-1 output at needed rows

// ----------------------------------------------------------------------------
__device__ __forceinline__ float blockReduce128(float v, volatile float* red) {
    #pragma unroll
    for (int o = 16; o; o >>= 1) v += __shfl_down_sync(0xffffffffu, v, o);
    int lane = threadIdx.x & 31, w = threadIdx.x >> 5;
    if (lane == 0) red[w] = v;
    __syncthreads();
    return red[0] + red[1] + red[2] + red[3];
}

// Constants + zero counters (runs first each call / each graph replay)
__global__ void k_const(const float* __restrict__ wr,
                        const float* __restrict__ b2,
                        const float* __restrict__ br) {
    __shared__ float red[4];
    int tid = threadIdx.x;
    float s = blockReduce128(wr[tid], red);
    float c = tanhf(b2[tid]);
    g_cbg[tid]  = c;
    g_base[tid] = s * c + br[0];
    if (tid == 0) { g_cnt1 = 0; g_cnt2 = 0; }
}

// Build active-token lists.
// A2 = {j : h[h[j]]==0}  (tokens whose delta feeds a kept output row)
// A1 = {j : h[h[h[j]]]==0} (tokens whose delta feeds a needed tok1 row)
__global__ void k_flags(const int* __restrict__ heads) {
    __shared__ int hs[S_];
    int b = blockIdx.x, j = threadIdx.x;
    hs[j] = heads[b * S_ + j];
    __syncthreads();
    int h1 = hs[j];
    int h2 = hs[h1];
    int h3 = hs[h2];
    int idx = b * S_ + j;
    if (h2 == 0) { int p = atomicAdd(&g_cnt2, 1); g_list2[p] = idx; }
    if (h3 == 0) { int p = atomicAdd(&g_cnt1, 1); g_list1[p] = idx; }
}

// tde partials: CTA (t, q) holds W1[t, 32q:32q+32, :] (8KB) in smem,
// loops over active tokens. W1 is read from global exactly once overall.
__global__ void k_tde(int level,
                      const float* __restrict__ tok_table,
                      const int*   __restrict__ tokens,
                      const float* __restrict__ dep_table,
                      const int*   __restrict__ dep_types) {
    const float* __restrict__ W1 = nullptr; // set below via param trick
    // (W1 passed as dep_table? no — pass explicitly)
    (void)W1;
    extern __shared__ float dummy_unused[]; (void)dummy_unused;
    // real body in k_tde_impl below
}

// NOTE: to keep things simple we define the real tde kernel with W1 param.
__global__ void k_tde2(int level,
                       const float* __restrict__ tok_table,
                       const int*   __restrict__ tokens,
                       const float* __restrict__ dep_table,
                       const int*   __restrict__ dep_types,
                       const float* __restrict__ W1) {
    const int t = blockIdx.x, q = blockIdx.y, tid = threadIdx.x;
    __shared__ float W1s[32 * E_];   // 2048 floats
    __shared__ float toks[32];
    __shared__ float deps[E_];
    __shared__ float red[4];

    const int  cnt  = (level == 1) ? g_cnt1  : g_cnt2;
    if (cnt == 0) return;
    const int* list = (level == 1) ? g_list1 : g_list2;

    const float* wb = W1 + (size_t)t * (D_ * E_) + q * 32 * E_;
    for (int k = tid; k < 32 * E_; k += 128) W1s[k] = wb[k];

    const int e0 = tid & 63;
    const int d0 = tid >> 6;

    for (int mi = 0; mi < cnt; ++mi) {
        __syncthreads();
        int idx = list[mi];
        if (tid < 32) {
            toks[tid] = (level == 1)
                ? tok_table[(size_t)tokens[idx] * D_ + q * 32 + tid]
                : g_tok1[idx * D_ + q * 32 + tid];
        } else if (tid < 96) {
            deps[tid - 32] = dep_table[dep_types[idx] * E_ + (tid - 32)];
        }
        __syncthreads();
        float de  = deps[e0];
        float acc = 0.f;
        #pragma unroll
        for (int i = 0; i < 16; ++i) {
            // linear index k = tid + 128*i -> d = d0 + 2*i, e = e0 (constant)
            acc += toks[d0 + 2 * i] * de * W1s[tid + 128 * i];
        }
        float tot = blockReduce128(acc, red);
        if (tid == 0) g_tpart[(q * NTOK + idx) * T_ + t] = tot;
    }
}

// Finalize tde: sum 4 partials + b1, tanh. Grid-stride over active list.
__global__ void k_ftde(int level, const float* __restrict__ b1) {
    int cnt  = (level == 1) ? g_cnt1  : g_cnt2;
    const int* list = (level == 1) ? g_list1 : g_list2;
    int t = threadIdx.x;
    for (int mi = blockIdx.x; mi < cnt; mi += gridDim.x) {
        int idx = list[mi];
        float s = g_tpart[idx * T_ + t]
                + g_tpart[(NTOK     + idx) * T_ + t]
                + g_tpart[(2 * NTOK + idx) * T_ + t]
                + g_tpart[(3 * NTOK + idx) * T_ + t]
                + b1[t];
        g_tde[idx * T_ + t] = tanhf(s);
    }
}

// c partials: CTA (p, q) holds W2[p, 32q:32q+32, :] (16KB) in smem.
// c[m,p] = sum_t tde[m,t] * (sum_d tok[m,d] * W2[p,d,t])
__global__ void k_c(int level,
                    const float* __restrict__ tok_table,
                    const int*   __restrict__ tokens,
                    const float* __restrict__ W2) {
    const int p = blockIdx.x, q = blockIdx.y, tid = threadIdx.x;
    __shared__ float W2s[32 * T_];   // 4096 floats
    __shared__ float toks[32];
    __shared__ float tdes[T_];
    __shared__ float red[4];

    const int  cnt  = (level == 1) ? g_cnt1  : g_cnt2;
    if (cnt == 0) return;
    const int* list = (level == 1) ? g_list1 : g_list2;

    const float* wb = W2 + (size_t)p * (D_ * T_) + q * 32 * T_;
    for (int k = tid; k < 32 * T_; k += 128) W2s[k] = wb[k];

    for (int mi = 0; mi < cnt; ++mi) {
        __syncthreads();
        int idx = list[mi];
        tdes[tid] = g_tde[idx * T_ + tid];
        if (tid < 32) {
            toks[tid] = (level == 1)
                ? tok_table[(size_t)tokens[idx] * D_ + q * 32 + tid]
                : g_tok1[idx * D_ + q * 32 + tid];
        }
        __syncthreads();
        float y = 0.f;
        #pragma unroll
        for (int dl = 0; dl < 32; ++dl) y += toks[dl] * W2s[dl * T_ + tid];
        float tot = blockReduce128(y * tdes[tid], red);
        if (tid == 0) g_cpart[(q * NTOK + idx) * D_ + p] = tot;
    }
}

// delta[j,p] = wr[j] * (tanh(c_raw + b2[p]) - cbg[p])
__global__ void k_delta(int level,
                        const float* __restrict__ wr,
                        const float* __restrict__ b2) {
    int cnt  = (level == 1) ? g_cnt1  : g_cnt2;
    const int* list = (level == 1) ? g_list1 : g_list2;
    int p = threadIdx.x;
    for (int mi = blockIdx.x; mi < cnt; mi += gridDim.x) {
        int idx = list[mi];
        int j   = idx & (S_ - 1);
        float s = g_cpart[idx * D_ + p]
                + g_cpart[(NTOK     + idx) * D_ + p]
                + g_cpart[(2 * NTOK + idx) * D_ + p]
                + g_cpart[(3 * NTOK + idx) * D_ + p]
                + b2[p];
        g_delta[idx * D_ + p] = wr[j] * (tanhf(s) - g_cbg[p]);
    }
}

// Block-1 output rows needed by level 2: tok1[i] = base + sum_{j:h[j]==i} delta1[j]
// Deterministic gather (fixed j order), no float atomics.
__global__ void k_scatter(const int* __restrict__ heads) {
    __shared__ int hs[S_];
    int tid = threadIdx.x;
    int cnt = g_cnt2;
    for (int mi = blockIdx.x; mi < cnt; mi += gridDim.x) {
        int idx = g_list2[mi];
        int b = idx >> 7, i = idx & 127;
        __syncthreads();
        hs[tid] = heads[b * S_ + tid];
        __syncthreads();
        float acc = g_base[tid];
        #pragma unroll 4
        for (int jp = 0; jp < S_; ++jp)
            if (hs[jp] == i) acc += g_delta[(b * S_ + jp) * D_ + tid];
        g_tok1[idx * D_ + tid] = acc;
    }
}

// Final output with root mask: rows with h[b,i]!=0 -> 0, else base + gather(delta2).
__global__ void k_out(const int* __restrict__ heads, float* __restrict__ out) {
    __shared__ int hs[S_];
    __shared__ int hi;
    int tid = threadIdx.x;
    int idx = blockIdx.x;
    int b = idx >> 7, i = idx & 127;
    if (tid == 0) hi = heads[idx];
    __syncthreads();
    if (hi != 0) { out[idx * D_ + tid] = 0.f; return; }
    hs[tid] = heads[b * S_ + tid];
    __syncthreads();
    float acc = g_base[tid];
    #pragma unroll 4
    for (int jp = 0; jp < S_; ++jp)
        if (hs[jp] == i) acc += g_delta[(b * S_ + jp) * D_ + tid];
    out[idx * D_ + tid] = acc;
}

// ----------------------------------------------------------------------------
extern "C" void kernel_launch(void* const* d_in, const int* in_sizes, int n_in,
                              void* d_out, int out_size) {
    const float* tok_table = (const float*)d_in[0];
    const float* dep_table = (const float*)d_in[1];
    const float* W1        = (const float*)d_in[2];
    const float* b1        = (const float*)d_in[3];
    const float* W2        = (const float*)d_in[4];
    const float* b2        = (const float*)d_in[5];
    const float* wr        = (const float*)d_in[6];
    const float* br        = (const float*)d_in[7];
    const int*   tokens    = (const int*)  d_in[8];
    const int*   dep_types = (const int*)  d_in[9];
    const int*   heads     = (const int*)  d_in[10];
    float*       out       = (float*)d_out;
    (void)in_sizes; (void)n_in; (void)out_size;

    k_const<<<1, 128>>>(wr, b2, br);
    k_flags<<<B_, S_>>>(heads);

    dim3 g4(T_, 4);
    for (int level = 1; level <= 2; ++level) {
        k_tde2 <<<g4, 128>>>(level, tok_table, tokens, dep_table, dep_types, W1);
        k_ftde <<<64, 128>>>(level, b1);
        k_c    <<<g4, 128>>>(level, tok_table, tokens, W2);
        k_delta<<<64, 128>>>(level, wr, b2);
        if (level == 1) k_scatter<<<64, 128>>>(heads);
    }
    k_out<<<NTOK, 128>>>(heads, out);
}

// round 5
// speedup vs baseline: 1.4242x; 1.4242x over previous
#include <cuda_runtime.h>
#include <math.h>

// Problem constants (fixed by dataset)
#define B_   16
#define S_   128
#define D_   128
#define E_   64
#define T_   128
#define NTOK (B_ * S_)   // 2048
#define NB   128         // grid size (one CTA per t / per p)
#define NT   128         // threads per CTA

// ----------------------------------------------------------------------------
// Scratch (static device globals; allocation-free)
// ----------------------------------------------------------------------------
__device__ int   g_cnt1, g_cnt2;
__device__ int   g_list1[NTOK], g_list2[NTOK];
__device__ float g_base[D_];                // sum(wr)*tanh(b2)+br
__device__ float g_tde  [NTOK * T_];        // tanh'd tde for active tokens
__device__ float g_delta[NTOK * D_];        // wr[j]*(c_nz - c_bg)
__device__ float g_tok1 [NTOK * D_];        // block-1 output at needed rows

// grid barrier state
__device__ unsigned          g_barCount = 0;
__device__ volatile unsigned g_barGen   = 0;

__device__ __forceinline__ void gsync(unsigned nb, unsigned& gen) {
    __syncthreads();
    if (threadIdx.x == 0) {
        __threadfence();
        unsigned arr = atomicAdd(&g_barCount, 1u);
        if (arr == nb - 1u) {
            g_barCount = 0u;
            __threadfence();
            g_barGen = gen + 1u;
        } else {
            while (g_barGen == gen) __nanosleep(64);
        }
    }
    gen += 1u;
    __syncthreads();
}

// ----------------------------------------------------------------------------
// One fused persistent kernel. Grid must be exactly NB CTAs (all co-resident:
// ~110KB dynamic smem -> <=2 CTA/SM, 128 CTAs <= 148 SMs -> single wave).
// Smem layout (floats):
//   [0, 8192)            W1s  : W1[bid, :, :]   (128 x 64)
//   [8192, 24576)        W2s  : W2[bid, :, :]   (128 x 128)
//   [24576, 26624)       hs   : heads (2048 ints)
//   [26624, 27136)       tokb : 4 warps x 128
//   [27136, 27392)       depb : 4 warps x 64
//   [27392, 27520)       wrs  : wr (128)
//   [27520, 27552)       red  : reduction scratch
// ----------------------------------------------------------------------------
#define SMEM_FLOATS 27552
#define SMEM_BYTES  (SMEM_FLOATS * 4)

__global__ void __launch_bounds__(NT, 1)
fused_kernel(const float* __restrict__ tok_table,
             const float* __restrict__ dep_table,
             const float* __restrict__ W1,
             const float* __restrict__ b1,
             const float* __restrict__ W2,
             const float* __restrict__ b2,
             const float* __restrict__ wr,
             const float* __restrict__ br,
             const int*   __restrict__ tokens,
             const int*   __restrict__ dep_types,
             const int*   __restrict__ heads,
             float*       __restrict__ out) {
    extern __shared__ float smem[];
    float* W1s  = smem;
    float* W2s  = smem + 8192;
    int*   hs   = (int*)(smem + 24576);
    float* tokb = smem + 26624;
    float* depb = smem + 27136;
    float* wrs  = smem + 27392;
    float* red  = smem + 27520;

    const int bid  = blockIdx.x;
    const int tid  = threadIdx.x;
    const int lane = tid & 31;
    const int w    = tid >> 5;
    const unsigned nb = gridDim.x;

    unsigned gen = g_barGen;   // read before any barrier bump -> race-free

    // ---------------- Phase 0: heads first (CTA0 needs them), then weights ---
    {
        const int4* hsrc = (const int4*)heads;
        int4* hd = (int4*)hs;
        #pragma unroll
        for (int k = tid; k < NTOK / 4; k += NT) hd[k] = hsrc[k];
        wrs[tid] = wr[tid];
    }
    __syncthreads();

    if (bid == 0) {
        // sum(wr) block reduce + constants + active lists
        float v = wrs[tid];
        #pragma unroll
        for (int o = 16; o; o >>= 1) v += __shfl_down_sync(0xffffffffu, v, o);
        if (lane == 0) red[w] = v;
        __syncthreads();
        float swr = red[0] + red[1] + red[2] + red[3];
        g_base[tid] = swr * tanhf(b2[tid]) + br[0];
        if (tid == 0) { g_cnt1 = 0; g_cnt2 = 0; }
        __syncthreads();
        for (int idx = tid; idx < NTOK; idx += NT) {
            int b7 = idx & ~(S_ - 1);
            int h1 = hs[idx];
            int h2 = hs[b7 + h1];
            int h3 = hs[b7 + h2];
            if (h2 == 0) g_list2[atomicAdd(&g_cnt2, 1)] = idx;
            if (h3 == 0) g_list1[atomicAdd(&g_cnt1, 1)] = idx;
        }
    }

    // weight preload (overlaps with CTA0's list build on other CTAs)
    {
        const float4* s1 = (const float4*)(W1 + (size_t)bid * D_ * E_);
        float4* d1 = (float4*)W1s;
        #pragma unroll
        for (int k = tid; k < (D_ * E_) / 4; k += NT) d1[k] = s1[k];
        const float4* s2 = (const float4*)(W2 + (size_t)bid * D_ * T_);
        float4* d2 = (float4*)W2s;
        #pragma unroll
        for (int k = tid; k < (D_ * T_) / 4; k += NT) d2[k] = s2[k];
    }

    // Early zero-write of masked output rows (h != 0): overlaps with DRAM
    // preload latency and CTA0's list build. Root rows written at the end.
    for (int r = bid; r < NTOK; r += nb) {
        if (hs[r] != 0) out[(size_t)r * D_ + tid] = 0.f;
    }
    gsync(nb, gen);

    const int cnt1 = *(volatile int*)&g_cnt1;
    const int cnt2 = *(volatile int*)&g_cnt2;
    const float b1t  = b1[bid];
    const float b2p  = b2[bid];
    const float cbgp = tanhf(b2p);

    for (int level = 1; level <= 2; ++level) {
        const int  cnt  = (level == 1) ? cnt1    : cnt2;
        const int* list = (level == 1) ? g_list1 : g_list2;

        // ---------- tde phase: CTA t = bid, warp-per-token --------------------
        for (int m0 = 0; m0 < cnt; m0 += 4) {
            int mi = m0 + w;
            int idx = (mi < cnt) ? list[mi] : -1;
            if (idx >= 0) {
                const float* trow = (level == 1)
                    ? tok_table + (size_t)tokens[idx] * D_
                    : g_tok1 + (size_t)idx * D_;
                #pragma unroll
                for (int d = lane; d < D_; d += 32) tokb[w * D_ + d] = trow[d];
                const float* drow = dep_table + (size_t)dep_types[idx] * E_;
                depb[w * E_ + lane]      = drow[lane];
                depb[w * E_ + lane + 32] = drow[lane + 32];
            }
            __syncwarp();
            if (idx >= 0) {
                float de0 = depb[w * E_ + lane];
                float de1 = depb[w * E_ + lane + 32];
                float acc = 0.f;
                #pragma unroll 8
                for (int d = 0; d < D_; ++d) {
                    float tv = tokb[w * D_ + d];
                    acc = fmaf(tv * de0, W1s[d * E_ + lane], acc);
                    acc = fmaf(tv * de1, W1s[d * E_ + lane + 32], acc);
                }
                #pragma unroll
                for (int o = 16; o; o >>= 1)
                    acc += __shfl_down_sync(0xffffffffu, acc, o);
                if (lane == 0) g_tde[(size_t)idx * T_ + bid] = tanhf(acc + b1t);
            }
            __syncwarp();
        }
        gsync(nb, gen);

        // ---------- c + delta phase: CTA p = bid, warp-per-token --------------
        for (int m0 = 0; m0 < cnt; m0 += 4) {
            int mi = m0 + w;
            int idx = (mi < cnt) ? list[mi] : -1;
            if (idx >= 0) {
                const float* trow = (level == 1)
                    ? tok_table + (size_t)tokens[idx] * D_
                    : g_tok1 + (size_t)idx * D_;
                #pragma unroll
                for (int d = lane; d < D_; d += 32) tokb[w * D_ + d] = trow[d];
            }
            __syncwarp();
            if (idx >= 0) {
                // lane covers t = 4*lane .. 4*lane+3
                float a0 = 0.f, a1 = 0.f, a2 = 0.f, a3 = 0.f;
                const float4* W2s4 = (const float4*)W2s;
                #pragma unroll 4
                for (int d = 0; d < D_; ++d) {
                    float tv = tokb[w * D_ + d];
                    float4 wv = W2s4[d * 32 + lane];
                    a0 = fmaf(tv, wv.x, a0);
                    a1 = fmaf(tv, wv.y, a1);
                    a2 = fmaf(tv, wv.z, a2);
                    a3 = fmaf(tv, wv.w, a3);
                }
                float4 tv4 = *(const float4*)(g_tde + (size_t)idx * T_ + lane * 4);
                float acc = a0 * tv4.x + a1 * tv4.y + a2 * tv4.z + a3 * tv4.w;
                #pragma unroll
                for (int o = 16; o; o >>= 1)
                    acc += __shfl_down_sync(0xffffffffu, acc, o);
                if (lane == 0) {
                    int j = idx & (S_ - 1);
                    g_delta[(size_t)idx * D_ + bid] =
                        wrs[j] * (tanhf(acc + b2p) - cbgp);
                }
            }
            __syncwarp();
        }
        gsync(nb, gen);

        // ---------- scatter (level 1 only): build tok1 rows for list2 ---------
        if (level == 1) {
            for (int mi = bid; mi < cnt2; mi += nb) {
                int idx = g_list2[mi];
                int b7  = idx & ~(S_ - 1);
                int i   = idx & (S_ - 1);
                float acc = g_base[tid];
                #pragma unroll 4
                for (int j = 0; j < S_; ++j)
                    if (hs[b7 + j] == i)
                        acc += g_delta[(size_t)(b7 + j) * D_ + tid];
                g_tok1[(size_t)idx * D_ + tid] = acc;
            }
            gsync(nb, gen);
        }
    }

    // -------- Output tail: only root rows (h == 0); zeros already written -----
    for (int r = bid; r < NTOK; r += nb) {
        if (hs[r] != 0) continue;
        int b7 = r & ~(S_ - 1);
        int i  = r & (S_ - 1);
        float val = g_base[tid];
        #pragma unroll 4
        for (int j = 0; j < S_; ++j)
            if (hs[b7 + j] == i)
                val += g_delta[(size_t)(b7 + j) * D_ + tid];
        out[(size_t)r * D_ + tid] = val;
    }
}

// ----------------------------------------------------------------------------
extern "C" void kernel_launch(void* const* d_in, const int* in_sizes, int n_in,
                              void* d_out, int out_size) {
    const float* tok_table = (const float*)d_in[0];
    const float* dep_table = (const float*)d_in[1];
    const float* W1        = (const float*)d_in[2];
    const float* b1        = (const float*)d_in[3];
    const float* W2        = (const float*)d_in[4];
    const float* b2        = (const float*)d_in[5];
    const float* wr        = (const float*)d_in[6];
    const float* br        = (const float*)d_in[7];
    const int*   tokens    = (const int*)  d_in[8];
    const int*   dep_types = (const int*)  d_in[9];
    const int*   heads     = (const int*)  d_in[10];
    float*       out       = (float*)d_out;
    (void)in_sizes; (void)n_in; (void)out_size;

    cudaFuncSetAttribute(fused_kernel,
                         cudaFuncAttributeMaxDynamicSharedMemorySize,
                         SMEM_BYTES);
    fused_kernel<<<NB, NT, SMEM_BYTES>>>(tok_table, dep_table, W1, b1, W2, b2,
                                         wr, br, tokens, dep_types, heads, out);
}

// round 8
// speedup vs baseline: 2.1896x; 1.5374x over previous
#include <cuda_runtime.h>
#include <math.h>

// Problem constants (fixed by dataset)
#define B_   16
#define S_   128
#define D_   128
#define E_   64
#define T_   128
#define NTOK (B_ * S_)   // 2048
#define NB   128         // grid: one CTA per t (tde) / per p (c)
#define NT   256         // 8 warps
#define NW   8

// ----------------------------------------------------------------------------
// Global scratch (allocation-free)
// ----------------------------------------------------------------------------
__device__ float g_tde   [NTOK * T_];   // tanh'd tde for active tokens (per level)
__device__ float g_delta [NTOK * D_];   // level-1 delta
__device__ float g_delta2[NTOK * D_];   // level-2 delta (separate: avoids alias)

// grid barrier state
__device__ unsigned          g_barCount = 0;
__device__ volatile unsigned g_barGen   = 0;

__device__ __forceinline__ void gsync(unsigned nb, unsigned& gen) {
    __syncthreads();
    if (threadIdx.x == 0) {
        __threadfence();
        unsigned arr = atomicAdd(&g_barCount, 1u);
        if (arr == nb - 1u) {
            g_barCount = 0u;
            __threadfence();
            g_barGen = gen + 1u;
        } else {
            while (g_barGen == gen) __nanosleep(64);
        }
    }
    gen += 1u;
    __syncthreads();
}

// ----------------------------------------------------------------------------
// Smem layout (float offsets)
// ----------------------------------------------------------------------------
#define OFF_W1   0        // 8192  : W1[bid,:,:]  (128 x 64)
#define OFF_W2   8192     // 16384 : W2[bid,:,:]  (128 x 128)
#define OFF_HS   24576    // 2048 ints : heads
#define OFF_L1   26624    // 2048 ints : list1
#define OFF_L2   28672    // 2048 ints : list2
#define OFF_TOKB 30720    // 8 warps x 2 tokens x 128
#define OFF_DEPB 32768    // 8 warps x 2 tokens x 64
#define OFF_BASE 33792    // 128
#define OFF_WRS  33920    // 128
#define OFF_CNT  34048    // 2 ints
#define OFF_RED  34052    // 4
#define SMEM_FLOATS 34064
#define SMEM_BYTES  (SMEM_FLOATS * 4)

// Build tok1 row for token idx into tb (lane covers d = lane + 32k).
// tok1[idx] = base + sum_{j asc: h[j]==pos(idx)} delta1[j]   (fixed j order)
__device__ __forceinline__ void build_tok1(float* tb, int idx, const int* hs,
                                           const float* base_s, int lane) {
    int b7 = idx & ~(S_ - 1), i = idx & (S_ - 1);
    float v0 = base_s[lane], v1 = base_s[lane + 32];
    float v2 = base_s[lane + 64], v3 = base_s[lane + 96];
    #pragma unroll 4
    for (int j = 0; j < S_; ++j) {
        if (hs[b7 + j] == i) {
            const float* dr = g_delta + (size_t)(b7 + j) * D_;
            v0 += dr[lane];      v1 += dr[lane + 32];
            v2 += dr[lane + 64]; v3 += dr[lane + 96];
        }
    }
    tb[lane] = v0; tb[lane + 32] = v1; tb[lane + 64] = v2; tb[lane + 96] = v3;
}

// ----------------------------------------------------------------------------
__global__ void __launch_bounds__(NT, 1)
fused_kernel(const float* __restrict__ tok_table,
             const float* __restrict__ dep_table,
             const float* __restrict__ W1,
             const float* __restrict__ b1,
             const float* __restrict__ W2,
             const float* __restrict__ b2,
             const float* __restrict__ wr,
             const float* __restrict__ br,
             const int*   __restrict__ tokens,
             const int*   __restrict__ dep_types,
             const int*   __restrict__ heads,
             float*       __restrict__ out) {
    extern __shared__ float smem[];
    float* W1s    = smem + OFF_W1;
    float* W2s    = smem + OFF_W2;
    int*   hs     = (int*)(smem + OFF_HS);
    int*   l1     = (int*)(smem + OFF_L1);
    int*   l2     = (int*)(smem + OFF_L2);
    float* tokb   = smem + OFF_TOKB;
    float* depb   = smem + OFF_DEPB;
    float* base_s = smem + OFF_BASE;
    float* wrs    = smem + OFF_WRS;
    int*   cnts   = (int*)(smem + OFF_CNT);
    float* red    = smem + OFF_RED;

    const int bid  = blockIdx.x;
    const int tid  = threadIdx.x;
    const int lane = tid & 31;
    const int w    = tid >> 5;
    const unsigned nb = gridDim.x;

    unsigned gen = g_barGen;   // read before any bump -> race-free

    // ---------------- Phase 0 (no cross-CTA deps): heads, consts, lists ------
    {
        const int4* hsrc = (const int4*)heads;
        int4* hd = (int4*)hs;
        #pragma unroll
        for (int k = tid; k < NTOK / 4; k += NT) hd[k] = hsrc[k];
        if (tid < 128) wrs[tid] = wr[tid];
        if (tid == 0) { cnts[0] = 0; cnts[1] = 0; }
    }
    __syncthreads();

    if (tid < 128) {
        float v = wrs[tid];
        #pragma unroll
        for (int o = 16; o; o >>= 1) v += __shfl_down_sync(0xffffffffu, v, o);
        if (lane == 0) red[w] = v;
    }
    __syncthreads();
    if (tid < 128) {
        float swr = red[0] + red[1] + red[2] + red[3];
        base_s[tid] = swr * tanhf(b2[tid]) + br[0];
    }
    // per-CTA redundant list build (order-independent results)
    for (int idx = tid; idx < NTOK; idx += NT) {
        int b7 = idx & ~(S_ - 1);
        int h1 = hs[idx];
        int h2 = hs[b7 + h1];
        int h3 = hs[b7 + h2];
        if (h2 == 0) l2[atomicAdd(&cnts[1], 1)] = idx;
        if (h3 == 0) l1[atomicAdd(&cnts[0], 1)] = idx;
    }
    // weight preload
    {
        const float4* s1 = (const float4*)(W1 + (size_t)bid * D_ * E_);
        float4* d1 = (float4*)W1s;
        #pragma unroll
        for (int k = tid; k < (D_ * E_) / 4; k += NT) d1[k] = s1[k];
        const float4* s2 = (const float4*)(W2 + (size_t)bid * D_ * T_);
        float4* d2 = (float4*)W2s;
        #pragma unroll
        for (int k = tid; k < (D_ * T_) / 4; k += NT) d2[k] = s2[k];
    }
    // early zero-write of masked output rows (overlaps with preload latency)
    for (int rr = (tid >> 7); rr < NTOK / NB; rr += 2) {
        int r = bid + NB * rr;
        if (hs[r] != 0) out[(size_t)r * D_ + (tid & 127)] = 0.f;
    }
    __syncthreads();

    const int cnt1 = cnts[0];
    const int cnt2 = cnts[1];
    const float b1t  = b1[bid];
    const float b2p  = b2[bid];
    const float cbgp = tanhf(b2p);

    for (int level = 1; level <= 2; ++level) {
        const int  cnt  = (level == 1) ? cnt1 : cnt2;
        const int* list = (level == 1) ? l1   : l2;
        float* dst      = (level == 1) ? g_delta : g_delta2;
        const bool reuse = (cnt <= 2 * NW);   // tokb survives into c phase

        // ---------- tde phase: CTA t = bid, 2 tokens per warp -----------------
        for (int g = w; 2 * g < cnt; g += NW) {
            int idx0 = list[2 * g];
            int idx1 = (2 * g + 1 < cnt) ? list[2 * g + 1] : -1;
            float* tb0 = tokb + (w * 2 + 0) * 128;
            float* tb1 = tokb + (w * 2 + 1) * 128;
            float* db0 = depb + (w * 2 + 0) * 64;
            float* db1 = depb + (w * 2 + 1) * 64;

            if (level == 1) {
                const float* tr0 = tok_table + (size_t)tokens[idx0] * D_;
                ((float4*)tb0)[lane] = ((const float4*)tr0)[lane];
                if (idx1 >= 0) {
                    const float* tr1 = tok_table + (size_t)tokens[idx1] * D_;
                    ((float4*)tb1)[lane] = ((const float4*)tr1)[lane];
                } else {
                    ((float4*)tb1)[lane] = make_float4(0.f, 0.f, 0.f, 0.f);
                }
            } else {
                build_tok1(tb0, idx0, hs, base_s, lane);
                if (idx1 >= 0) build_tok1(tb1, idx1, hs, base_s, lane);
                else { tb1[lane] = 0.f; tb1[lane+32] = 0.f; tb1[lane+64] = 0.f; tb1[lane+96] = 0.f; }
            }
            if (lane < 16) {
                const float* dr0 = dep_table + (size_t)dep_types[idx0] * E_;
                ((float4*)db0)[lane] = ((const float4*)dr0)[lane];
                if (idx1 >= 0) {
                    const float* dr1 = dep_table + (size_t)dep_types[idx1] * E_;
                    ((float4*)db1)[lane] = ((const float4*)dr1)[lane];
                } else {
                    ((float4*)db1)[lane] = make_float4(0.f, 0.f, 0.f, 0.f);
                }
            }
            __syncwarp();

            float de00 = db0[lane], de01 = db0[lane + 32];
            float de10 = db1[lane], de11 = db1[lane + 32];
            float a00 = 0.f, a01 = 0.f, a10 = 0.f, a11 = 0.f;
            #pragma unroll 8
            for (int d = 0; d < D_; ++d) {
                float w0 = W1s[d * E_ + lane];
                float w1 = W1s[d * E_ + lane + 32];
                float t0 = tb0[d];
                float t1 = tb1[d];
                a00 = fmaf(t0 * de00, w0, a00);
                a01 = fmaf(t0 * de01, w1, a01);
                a10 = fmaf(t1 * de10, w0, a10);
                a11 = fmaf(t1 * de11, w1, a11);
            }
            float s0 = a00 + a01, s1 = a10 + a11;
            #pragma unroll
            for (int o = 16; o; o >>= 1) {
                s0 += __shfl_down_sync(0xffffffffu, s0, o);
                s1 += __shfl_down_sync(0xffffffffu, s1, o);
            }
            if (lane == 0) {
                g_tde[(size_t)idx0 * T_ + bid] = tanhf(s0 + b1t);
                if (idx1 >= 0) g_tde[(size_t)idx1 * T_ + bid] = tanhf(s1 + b1t);
            }
            __syncwarp();
        }
        gsync(nb, gen);

        // ---------- c + delta phase: CTA p = bid, 2 tokens per warp -----------
        for (int g = w; 2 * g < cnt; g += NW) {
            int idx0 = list[2 * g];
            int idx1 = (2 * g + 1 < cnt) ? list[2 * g + 1] : -1;
            float* tb0 = tokb + (w * 2 + 0) * 128;
            float* tb1 = tokb + (w * 2 + 1) * 128;

            if (!reuse) {   // tokb stale (multiple groups per warp): rebuild
                if (level == 1) {
                    const float* tr0 = tok_table + (size_t)tokens[idx0] * D_;
                    ((float4*)tb0)[lane] = ((const float4*)tr0)[lane];
                    if (idx1 >= 0) {
                        const float* tr1 = tok_table + (size_t)tokens[idx1] * D_;
                        ((float4*)tb1)[lane] = ((const float4*)tr1)[lane];
                    } else {
                        ((float4*)tb1)[lane] = make_float4(0.f, 0.f, 0.f, 0.f);
                    }
                } else {
                    build_tok1(tb0, idx0, hs, base_s, lane);
                    if (idx1 >= 0) build_tok1(tb1, idx1, hs, base_s, lane);
                    else { tb1[lane] = 0.f; tb1[lane+32] = 0.f; tb1[lane+64] = 0.f; tb1[lane+96] = 0.f; }
                }
                __syncwarp();
            }

            float4 tv0 = *(const float4*)(g_tde + (size_t)idx0 * T_ + lane * 4);
            float4 tv1 = (idx1 >= 0)
                ? *(const float4*)(g_tde + (size_t)idx1 * T_ + lane * 4)
                : make_float4(0.f, 0.f, 0.f, 0.f);

            float a00 = 0.f, a01 = 0.f, a02 = 0.f, a03 = 0.f;
            float a10 = 0.f, a11 = 0.f, a12 = 0.f, a13 = 0.f;
            const float4* W2s4 = (const float4*)W2s;
            #pragma unroll 4
            for (int d = 0; d < D_; ++d) {
                float4 wv = W2s4[d * 32 + lane];
                float t0 = tb0[d];
                float t1 = tb1[d];
                a00 = fmaf(t0, wv.x, a00); a01 = fmaf(t0, wv.y, a01);
                a02 = fmaf(t0, wv.z, a02); a03 = fmaf(t0, wv.w, a03);
                a10 = fmaf(t1, wv.x, a10); a11 = fmaf(t1, wv.y, a11);
                a12 = fmaf(t1, wv.z, a12); a13 = fmaf(t1, wv.w, a13);
            }
            float s0 = a00 * tv0.x + a01 * tv0.y + a02 * tv0.z + a03 * tv0.w;
            float s1 = a10 * tv1.x + a11 * tv1.y + a12 * tv1.z + a13 * tv1.w;
            #pragma unroll
            for (int o = 16; o; o >>= 1) {
                s0 += __shfl_down_sync(0xffffffffu, s0, o);
                s1 += __shfl_down_sync(0xffffffffu, s1, o);
            }
            if (lane == 0) {
                dst[(size_t)idx0 * D_ + bid] =
                    wrs[idx0 & (S_ - 1)] * (tanhf(s0 + b2p) - cbgp);
                if (idx1 >= 0)
                    dst[(size_t)idx1 * D_ + bid] =
                        wrs[idx1 & (S_ - 1)] * (tanhf(s1 + b2p) - cbgp);
            }
            __syncwarp();
        }
        gsync(nb, gen);
    }

    // -------- Output tail: root rows only (zeros written in phase 0) ----------
    for (int rr = (tid >> 7); rr < NTOK / NB; rr += 2) {
        int r = bid + NB * rr;
        if (hs[r] != 0) continue;
        int col = tid & 127;
        int b7 = r & ~(S_ - 1), i = r & (S_ - 1);
        float v = base_s[col];
        #pragma unroll 4
        for (int j = 0; j < S_; ++j)
            if (hs[b7 + j] == i)
                v += g_delta2[(size_t)(b7 + j) * D_ + col];
        out[(size_t)r * D_ + col] = v;
    }
}

// ----------------------------------------------------------------------------
extern "C" void kernel_launch(void* const* d_in, const int* in_sizes, int n_in,
                              void* d_out, int out_size) {
    const float* tok_table = (const float*)d_in[0];
    const float* dep_table = (const float*)d_in[1];
    const float* W1        = (const float*)d_in[2];
    const float* b1        = (const float*)d_in[3];
    const float* W2        = (const float*)d_in[4];
    const float* b2        = (const float*)d_in[5];
    const float* wr        = (const float*)d_in[6];
    const float* br        = (const float*)d_in[7];
    const int*   tokens    = (const int*)  d_in[8];
    const int*   dep_types = (const int*)  d_in[9];
    const int*   heads     = (const int*)  d_in[10];
    float*       out       = (float*)d_out;
    (void)in_sizes; (void)n_in; (void)out_size;

    cudaFuncSetAttribute(fused_kernel,
                         cudaFuncAttributeMaxDynamicSharedMemorySize,
                         SMEM_BYTES);
    fused_kernel<<<NB, NT, SMEM_BYTES>>>(tok_table, dep_table, W1, b1, W2, b2,
                                         wr, br, tokens, dep_types, heads, out);
}